// round 14
// baseline (speedup 1.0000x reference)
#include <cuda_runtime.h>
#include <cuda_fp16.h>
#include <cstdint>
#include <cstddef>

// ---------------------------------------------------------------------------
// Problem constants
// ---------------------------------------------------------------------------
constexpr int B_ = 256;   // batches
constexpr int N_ = 1024;  // patches
constexpr int M_ = 128;   // words
constexpr int C_ = 512;   // channels (K)

constexpr int NTILE  = 256;          // patch tile (CTA N)
constexpr int NTILES = N_ / NTILE;   // 4
constexpr int KC     = 16;           // K chunk (fp32 elements)
constexpr int KCH    = C_ / KC;      // 32 chunks per tile
constexpr int GTOT   = NTILES * KCH; // 128 chunks
constexpr int SPH    = 24;           // smem row stride in halfs (16 + 8 pad) = 48 B

// Stage buffers: A = 128x16 fp16, B = 256x16 fp16 (48B rows), double buffered
constexpr int A_SM_BYTES  = 128 * SPH * 2;           // 6144
constexpr int B_SM_BYTES  = 256 * SPH * 2;           // 12288
constexpr int STAGE_BYTES = A_SM_BYTES + B_SM_BYTES; // 18432
constexpr int OFF_Bt      = A_SM_BYTES;

// Float-indexed regions after the two stage buffers (byte 36864)
constexpr int MASKF   = (2 * STAGE_BYTES) / 4;   // 9216 (1024 floats)
constexpr int COLWF   = MASKF + 1024;            // 2(wm) x 256 floats
constexpr int ROWREDF = COLWF + 512;             // 128 x 4(wn) floats
constexpr int REDF    = ROWREDF + 512;           // 32 floats
constexpr int SMEM_BYTES = (REDF + 32) * 4;      // 45184

// ---------------------------------------------------------------------------
// Helpers
// ---------------------------------------------------------------------------
__device__ __forceinline__ uint32_t smem_u32(const void* p) {
    uint32_t a;
    asm("{ .reg .u64 t; cvta.to.shared.u64 t, %1; cvt.u32.u64 %0, t; }"
        : "=r"(a) : "l"(p));
    return a;
}

__device__ __forceinline__ void ldm4(uint32_t* r, uint32_t addr) {
    asm volatile("ldmatrix.sync.aligned.m8n8.x4.shared.b16 {%0,%1,%2,%3}, [%4];"
                 : "=r"(r[0]), "=r"(r[1]), "=r"(r[2]), "=r"(r[3]) : "r"(addr));
}

// m16n8k16 row.col fp16 mma, fp32 accumulate (C==D)
__device__ __forceinline__ void mma16(float* c, const uint32_t* a,
                                      uint32_t b0, uint32_t b1) {
    asm volatile(
        "mma.sync.aligned.m16n8k16.row.col.f32.f16.f16.f32 "
        "{%0,%1,%2,%3}, {%4,%5,%6,%7}, {%8,%9}, {%0,%1,%2,%3};"
        : "+f"(c[0]), "+f"(c[1]), "+f"(c[2]), "+f"(c[3])
        : "r"(a[0]), "r"(a[1]), "r"(a[2]), "r"(a[3]), "r"(b0), "r"(b1));
}

// ---------------------------------------------------------------------------
// Kernel: one CTA per batch; 256 threads = 8 warps (2 M x 4 N).
// Warp tile m64 x n64 (fragment traffic 1/m+1/n = 0.031, -33% vs m32n64).
// CTA tile 128(M) x 256(N). K in 32 chunks of 16. Two-iteration register
// pipeline (STS never stalls on LDG); patch streamed with __ldcs.
// ---------------------------------------------------------------------------
__global__ void __launch_bounds__(256)
hrpa_kernel(const float* __restrict__ patch,   // (B, N, C)
            const float* __restrict__ word,    // (B, M, C)
            const float* __restrict__ mask,    // (B, N)
            float* __restrict__ out)           // (B, 1)
{
    extern __shared__ char smc[];
    float* fsm = reinterpret_cast<float*>(smc);
    const uint32_t smb = smem_u32(smc);

    const int tid  = threadIdx.x;
    const int lane = tid & 31;
    const int w    = tid >> 5;     // 0..7
    const int wm   = w & 1;        // M direction (rows wm*64 .. +63)
    const int wn   = w >> 1;       // N direction (cols wn*64 .. +63)
    const int g    = lane >> 2;    // quad group 0..7
    const int tig  = lane & 3;     // thread in group
    const int b    = blockIdx.x;

    // ldmatrix per-thread offsets (half units, SPH=24 rows)
    const int mi = lane >> 3, r8 = lane & 7;
    const int aoff = (((mi & 1) << 3) + r8) * SPH + ((mi >> 1) << 3);
    const int boff = (((mi >> 1) << 3) + r8) * SPH + ((mi & 1) << 3);

    const float* wbase = word  + (size_t)b * M_ * C_;
    const float* pbase = patch + (size_t)b * N_ * C_;

    // loader mapping: 16 floats/row = 4 vec4; lr = tid>>2 (0..63), lv = tid&3
    const int lr = tid >> 2;
    const int lv = tid & 3;

    // ---- mask -> smem, accumulate mask sum ----
    float masksum = 0.f;
    for (int i = tid; i < N_; i += 256) {
        float m = mask[b * N_ + i];
        fsm[MASKF + i] = m;
        masksum += m;
    }

    auto load_regs = [&](int gq, float4* stA, float4* stB) {
        const int nt = gq >> 5;            // gq / KCH
        const int k0 = (gq & 31) * KC;
        #pragma unroll
        for (int p = 0; p < 2; p++) {      // A (word): L2-resident
            const int r = p * 64 + lr;
            stA[p] = *(const float4*)(wbase + (size_t)r * C_ + k0 + lv * 4);
        }
        #pragma unroll
        for (int p = 0; p < 4; p++) {      // B (patch): streaming
            const int r = p * 64 + lr;
            stB[p] = __ldcs((const float4*)(pbase + (size_t)(nt * NTILE + r) * C_ + k0 + lv * 4));
        }
    };
    auto sts_stage = [&](int buf, const float4* stA, const float4* stB) {
        char* base = smc + buf * STAGE_BYTES;
        #pragma unroll
        for (int p = 0; p < 2; p++) {
            const int r = p * 64 + lr;
            __half2 h0 = __floats2half2_rn(stA[p].x, stA[p].y);
            __half2 h1 = __floats2half2_rn(stA[p].z, stA[p].w);
            *(uint2*)(base + (r * SPH + lv * 4) * 2) =
                make_uint2(*(uint32_t*)&h0, *(uint32_t*)&h1);
        }
        #pragma unroll
        for (int p = 0; p < 4; p++) {
            const int r = p * 64 + lr;
            __half2 h0 = __floats2half2_rn(stB[p].x, stB[p].y);
            __half2 h1 = __floats2half2_rn(stB[p].z, stB[p].w);
            *(uint2*)(base + OFF_Bt + (r * SPH + lv * 4) * 2) =
                make_uint2(*(uint32_t*)&h0, *(uint32_t*)&h1);
        }
    };

    // ---- prologue: chunk 0 -> buffer 0; chunk 1 held in registers ----
    float4 sA[2], sB[4];        // live across iterations (2-iter pipeline)
    load_regs(0, sA, sB);
    sts_stage(0, sA, sB);       // one-time LDG stall
    load_regs(1, sA, sB);
    __syncthreads();

    float rmax[8];              // rows wm*64 + mt*16 + {g, g+8}, mt=0..3
    #pragma unroll
    for (int i = 0; i < 8; i++) rmax[i] = -3.0e38f;
    float colsum = 0.f;

    for (int nt = 0; nt < NTILES; nt++) {
        float acc[4][8][4];     // [mt][j][quad] : m64 x n64, 128 floats
        #pragma unroll
        for (int mt = 0; mt < 4; mt++)
            #pragma unroll
            for (int j = 0; j < 8; j++)
                #pragma unroll
                for (int q = 0; q < 4; q++) acc[mt][j][q] = 0.f;

        for (int kc = 0; kc < KCH; kc++) {
            const int gq = nt * KCH + kc;

            // 1. STS chunk gq+1 from registers loaded last iteration (no stall)
            if (gq + 1 < GTOT) sts_stage((gq + 1) & 1, sA, sB);
            // 2. LDGs for chunk gq+2 (two iterations of slack)
            if (gq + 2 < GTOT) load_regs(gq + 2, sA, sB);

            // 3. MMAs on chunk gq from buffer gq&1 (k16: one ks block)
            const uint32_t abase = smb + (uint32_t)((gq & 1) * STAGE_BYTES);
            const uint32_t bbase = abase + OFF_Bt;

            uint32_t Af[4][4];
            #pragma unroll
            for (int mt = 0; mt < 4; mt++)
                ldm4(Af[mt], abase + (uint32_t)(((wm * 64 + mt * 16) * SPH) + aoff) * 2);
            #pragma unroll
            for (int jj = 0; jj < 4; jj++) {
                uint32_t Bf[4];
                ldm4(Bf, bbase + (uint32_t)(((wn * 64 + jj * 16) * SPH) + boff) * 2);
                #pragma unroll
                for (int mt = 0; mt < 4; mt++) {
                    mma16(acc[mt][jj * 2    ], Af[mt], Bf[0], Bf[1]);
                    mma16(acc[mt][jj * 2 + 1], Af[mt], Bf[2], Bf[3]);
                }
            }
            __syncthreads();
        }

        // ---- epilogue for this ntile ----
        // Thread owns rows {wm*64+mt*16+g, +8} (mt=0..3), cols {wn*64+j*8+2tig, +1}.
        const int n0 = nt * NTILE;
        float colpart[16];
        #pragma unroll
        for (int j = 0; j < 8; j++) {
            #pragma unroll
            for (int cc = 0; cc < 2; cc++) {
                const int col = wn * 64 + j * 8 + 2 * tig + cc;
                const float pen = 1000.f * (1.f - fsm[MASKF + n0 + col]);
                float vmax = -3.0e38f;
                #pragma unroll
                for (int mt = 0; mt < 4; mt++) {
                    float v0 = acc[mt][j][cc];      // row m0+g
                    float v1 = acc[mt][j][cc + 2];  // row m0+8+g
                    v0 = v0 > 0.f ? v0 : 0.1f * v0;
                    v1 = v1 > 0.f ? v1 : 0.1f * v1;
                    rmax[mt * 2 + 0] = fmaxf(rmax[mt * 2 + 0], v0 - pen);
                    rmax[mt * 2 + 1] = fmaxf(rmax[mt * 2 + 1], v1 - pen);
                    vmax = fmaxf(vmax, fmaxf(v0, v1));
                }
                colpart[j * 2 + cc] = vmax;
            }
        }
        // column max across the 8 quad-groups (lanes differing in g)
        #pragma unroll
        for (int off = 4; off <= 16; off <<= 1)
            #pragma unroll
            for (int i = 0; i < 16; i++)
                colpart[i] = fmaxf(colpart[i], __shfl_xor_sync(0xffffffffu, colpart[i], off));
        if (g == 0) {
            #pragma unroll
            for (int j = 0; j < 8; j++)
                #pragma unroll
                for (int cc = 0; cc < 2; cc++)
                    fsm[COLWF + wm * NTILE + wn * 64 + j * 8 + 2 * tig + cc] =
                        colpart[j * 2 + cc];
        }
        __syncthreads();
        {
            const int c = tid;   // 0..255
            const float cm = fmaxf(fsm[COLWF + c], fsm[COLWF + NTILE + c]);
            colsum += cm * fsm[MASKF + n0 + c];
        }
        __syncthreads();
    }

    // ---- row-max combine (within quad, then across wn groups) ----
    #pragma unroll
    for (int off = 1; off <= 2; off <<= 1)
        #pragma unroll
        for (int i = 0; i < 8; i++)
            rmax[i] = fmaxf(rmax[i], __shfl_xor_sync(0xffffffffu, rmax[i], off));
    if (tig == 0) {
        #pragma unroll
        for (int mt = 0; mt < 4; mt++) {
            fsm[ROWREDF + (wm * 64 + mt * 16 +     g) * 4 + wn] = rmax[mt * 2 + 0];
            fsm[ROWREDF + (wm * 64 + mt * 16 + 8 + g) * 4 + wn] = rmax[mt * 2 + 1];
        }
    }
    __syncthreads();

    float rpart = 0.f;
    if (tid < 128) {
        rpart = fmaxf(fmaxf(fsm[ROWREDF + tid * 4 + 0], fsm[ROWREDF + tid * 4 + 1]),
                      fmaxf(fsm[ROWREDF + tid * 4 + 2], fsm[ROWREDF + tid * 4 + 3]));
    }

    // ---- block reduction of rpart / colsum / masksum ----
    #pragma unroll
    for (int off = 16; off > 0; off >>= 1) {
        rpart   += __shfl_down_sync(0xffffffffu, rpart,   off);
        colsum  += __shfl_down_sync(0xffffffffu, colsum,  off);
        masksum += __shfl_down_sync(0xffffffffu, masksum, off);
    }
    if (lane == 0) {
        fsm[REDF + w * 4 + 0] = rpart;
        fsm[REDF + w * 4 + 1] = colsum;
        fsm[REDF + w * 4 + 2] = masksum;
    }
    __syncthreads();
    if (tid == 0) {
        float rs = 0.f, cs = 0.f, ms = 0.f;
        #pragma unroll
        for (int i = 0; i < 8; i++) {
            rs += fsm[REDF + i * 4 + 0];
            cs += fsm[REDF + i * 4 + 1];
            ms += fsm[REDF + i * 4 + 2];
        }
        out[b] = rs * (1.f / 128.f) + cs / (ms + 1e-8f);
    }
}

// ---------------------------------------------------------------------------
// Host launch
// ---------------------------------------------------------------------------
extern "C" void kernel_launch(void* const* d_in, const int* in_sizes, int n_in,
                              void* d_out, int out_size)
{
    (void)in_sizes; (void)n_in; (void)out_size;
    const float* patch = (const float*)d_in[0];  // (B, N, C)
    const float* word  = (const float*)d_in[1];  // (B, M, C)
    const float* mask  = (const float*)d_in[2];  // (B, N)
    float* out = (float*)d_out;                  // (B, 1)

    cudaFuncSetAttribute(hrpa_kernel,
                         cudaFuncAttributeMaxDynamicSharedMemorySize, SMEM_BYTES);
    hrpa_kernel<<<B_, 256, SMEM_BYTES>>>(patch, word, mask, out);
}

// round 15
// speedup vs baseline: 1.3459x; 1.3459x over previous
#include <cuda_runtime.h>
#include <cuda_fp16.h>
#include <cstdint>
#include <cstddef>

// ---------------------------------------------------------------------------
// Problem constants
// ---------------------------------------------------------------------------
constexpr int B_ = 256;   // batches
constexpr int N_ = 1024;  // patches
constexpr int M_ = 128;   // words
constexpr int C_ = 512;   // channels (K)

constexpr int NTILE  = 256;          // patch tile (CTA N)
constexpr int NTILES = N_ / NTILE;   // 4
constexpr int KC     = 16;           // K chunk (fp32 elements)
constexpr int KCH    = C_ / KC;      // 32 chunks per tile
constexpr int GTOT   = NTILES * KCH; // 128 chunks
constexpr int SPH    = 24;           // smem row stride in halfs (16 + 8 pad) = 48 B

// Stage buffers: A = 128x16 fp16, B = 256x16 fp16 (48B rows), double buffered
constexpr int A_SM_BYTES  = 128 * SPH * 2;           // 6144
constexpr int B_SM_BYTES  = 256 * SPH * 2;           // 12288
constexpr int STAGE_BYTES = A_SM_BYTES + B_SM_BYTES; // 18432
constexpr int OFF_Bt      = A_SM_BYTES;

// Float-indexed regions after the two stage buffers (byte 36864)
constexpr int MASKF   = (2 * STAGE_BYTES) / 4;   // 9216 (1024 floats)
constexpr int COLWF   = MASKF + 1024;            // 2(wm) x 256 floats
constexpr int ROWREDF = COLWF + 512;             // 128 x 4(wn) floats
constexpr int REDF    = ROWREDF + 512;           // 32 floats
constexpr int SMEM_BYTES = (REDF + 32) * 4;      // 45184 (~44 KB; 2 CTAs/SM)

// ---------------------------------------------------------------------------
// Helpers
// ---------------------------------------------------------------------------
__device__ __forceinline__ uint32_t smem_u32(const void* p) {
    uint32_t a;
    asm("{ .reg .u64 t; cvta.to.shared.u64 t, %1; cvt.u32.u64 %0, t; }"
        : "=r"(a) : "l"(p));
    return a;
}

__device__ __forceinline__ void ldm4(uint32_t* r, uint32_t addr) {
    asm volatile("ldmatrix.sync.aligned.m8n8.x4.shared.b16 {%0,%1,%2,%3}, [%4];"
                 : "=r"(r[0]), "=r"(r[1]), "=r"(r[2]), "=r"(r[3]) : "r"(addr));
}

// m16n8k16 row.col fp16 mma, fp16 accumulate (C==D, 2 packed regs)
__device__ __forceinline__ void mma16h(uint32_t& c0, uint32_t& c1,
                                       const uint32_t* a,
                                       uint32_t b0, uint32_t b1) {
    asm volatile(
        "mma.sync.aligned.m16n8k16.row.col.f16.f16.f16.f16 "
        "{%0,%1}, {%2,%3,%4,%5}, {%6,%7}, {%0,%1};"
        : "+r"(c0), "+r"(c1)
        : "r"(a[0]), "r"(a[1]), "r"(a[2]), "r"(a[3]), "r"(b0), "r"(b1));
}

// ---------------------------------------------------------------------------
// Kernel: one CTA per batch; 256 threads = 8 warps (2 M x 4 N); 2 CTAs/SM.
// Warp tile m64 x n64 with fp16 accumulators (64 regs -> fits 128-reg cap).
// CTA tile 128(M) x 256(N). K in 32 chunks of 16. Two-iteration register
// pipeline (STS never stalls on LDG); patch streamed with __ldcs.
// ---------------------------------------------------------------------------
__global__ void __launch_bounds__(256, 2)
hrpa_kernel(const float* __restrict__ patch,   // (B, N, C)
            const float* __restrict__ word,    // (B, M, C)
            const float* __restrict__ mask,    // (B, N)
            float* __restrict__ out)           // (B, 1)
{
    extern __shared__ char smc[];
    float* fsm = reinterpret_cast<float*>(smc);
    const uint32_t smb = smem_u32(smc);

    const int tid  = threadIdx.x;
    const int lane = tid & 31;
    const int w    = tid >> 5;     // 0..7
    const int wm   = w & 1;        // M direction (rows wm*64 .. +63)
    const int wn   = w >> 1;       // N direction (cols wn*64 .. +63)
    const int g    = lane >> 2;    // quad group 0..7
    const int tig  = lane & 3;     // thread in group
    const int b    = blockIdx.x;

    // ldmatrix per-thread offsets (half units, SPH=24 rows)
    const int mi = lane >> 3, r8 = lane & 7;
    const int aoff = (((mi & 1) << 3) + r8) * SPH + ((mi >> 1) << 3);
    const int boff = (((mi >> 1) << 3) + r8) * SPH + ((mi & 1) << 3);

    const float* wbase = word  + (size_t)b * M_ * C_;
    const float* pbase = patch + (size_t)b * N_ * C_;

    // loader mapping: 16 floats/row = 4 vec4; lr = tid>>2 (0..63), lv = tid&3
    const int lr = tid >> 2;
    const int lv = tid & 3;

    // ---- mask -> smem, accumulate mask sum ----
    float masksum = 0.f;
    for (int i = tid; i < N_; i += 256) {
        float m = mask[b * N_ + i];
        fsm[MASKF + i] = m;
        masksum += m;
    }

    auto load_regs = [&](int gq, float4* stA, float4* stB) {
        const int nt = gq >> 5;            // gq / KCH
        const int k0 = (gq & 31) * KC;
        #pragma unroll
        for (int p = 0; p < 2; p++) {      // A (word): L2-resident
            const int r = p * 64 + lr;
            stA[p] = *(const float4*)(wbase + (size_t)r * C_ + k0 + lv * 4);
        }
        #pragma unroll
        for (int p = 0; p < 4; p++) {      // B (patch): streaming
            const int r = p * 64 + lr;
            stB[p] = __ldcs((const float4*)(pbase + (size_t)(nt * NTILE + r) * C_ + k0 + lv * 4));
        }
    };
    auto sts_stage = [&](int buf, const float4* stA, const float4* stB) {
        char* base = smc + buf * STAGE_BYTES;
        #pragma unroll
        for (int p = 0; p < 2; p++) {
            const int r = p * 64 + lr;
            __half2 h0 = __floats2half2_rn(stA[p].x, stA[p].y);
            __half2 h1 = __floats2half2_rn(stA[p].z, stA[p].w);
            *(uint2*)(base + (r * SPH + lv * 4) * 2) =
                make_uint2(*(uint32_t*)&h0, *(uint32_t*)&h1);
        }
        #pragma unroll
        for (int p = 0; p < 4; p++) {
            const int r = p * 64 + lr;
            __half2 h0 = __floats2half2_rn(stB[p].x, stB[p].y);
            __half2 h1 = __floats2half2_rn(stB[p].z, stB[p].w);
            *(uint2*)(base + OFF_Bt + (r * SPH + lv * 4) * 2) =
                make_uint2(*(uint32_t*)&h0, *(uint32_t*)&h1);
        }
    };

    // ---- prologue: chunk 0 -> buffer 0; chunk 1 held in registers ----
    float4 sA[2], sB[4];        // live across iterations (2-iter pipeline)
    load_regs(0, sA, sB);
    sts_stage(0, sA, sB);       // one-time LDG stall
    load_regs(1, sA, sB);
    __syncthreads();

    float rmax[8];              // rows wm*64 + mt*16 + {g, g+8}, mt=0..3
    #pragma unroll
    for (int i = 0; i < 8; i++) rmax[i] = -3.0e38f;
    float colsum = 0.f;

    for (int nt = 0; nt < NTILES; nt++) {
        // fp16x2 accumulators: [mt][j][0] = (c0,c1) row g; [1] = (c2,c3) row g+8
        uint32_t acc[4][8][2];
        #pragma unroll
        for (int mt = 0; mt < 4; mt++)
            #pragma unroll
            for (int j = 0; j < 8; j++) { acc[mt][j][0] = 0u; acc[mt][j][1] = 0u; }

        for (int kc = 0; kc < KCH; kc++) {
            const int gq = nt * KCH + kc;

            // 1. STS chunk gq+1 from registers loaded last iteration (no stall)
            if (gq + 1 < GTOT) sts_stage((gq + 1) & 1, sA, sB);
            // 2. LDGs for chunk gq+2 (two iterations of slack)
            if (gq + 2 < GTOT) load_regs(gq + 2, sA, sB);

            // 3. MMAs on chunk gq from buffer gq&1 (k16)
            const uint32_t abase = smb + (uint32_t)((gq & 1) * STAGE_BYTES);
            const uint32_t bbase = abase + OFF_Bt;

            uint32_t Af[4][4];
            #pragma unroll
            for (int mt = 0; mt < 4; mt++)
                ldm4(Af[mt], abase + (uint32_t)(((wm * 64 + mt * 16) * SPH) + aoff) * 2);
            #pragma unroll
            for (int jj = 0; jj < 4; jj++) {
                uint32_t Bf[4];
                ldm4(Bf, bbase + (uint32_t)(((wn * 64 + jj * 16) * SPH) + boff) * 2);
                #pragma unroll
                for (int mt = 0; mt < 4; mt++) {
                    mma16h(acc[mt][jj * 2    ][0], acc[mt][jj * 2    ][1], Af[mt], Bf[0], Bf[1]);
                    mma16h(acc[mt][jj * 2 + 1][0], acc[mt][jj * 2 + 1][1], Af[mt], Bf[2], Bf[3]);
                }
            }
            __syncthreads();
        }

        // ---- epilogue for this ntile ----
        // Thread owns rows {wm*64+mt*16+g, +8} (mt=0..3), cols {wn*64+j*8+2tig, +1}.
        const int n0 = nt * NTILE;
        float colpart[16];
        #pragma unroll
        for (int j = 0; j < 8; j++) {
            float2 va[4], vb[4];
            #pragma unroll
            for (int mt = 0; mt < 4; mt++) {
                va[mt] = __half22float2(*reinterpret_cast<__half2*>(&acc[mt][j][0]));
                vb[mt] = __half22float2(*reinterpret_cast<__half2*>(&acc[mt][j][1]));
            }
            #pragma unroll
            for (int cc = 0; cc < 2; cc++) {
                const int col = wn * 64 + j * 8 + 2 * tig + cc;
                const float pen = 1000.f * (1.f - fsm[MASKF + n0 + col]);
                float vmax = -3.0e38f;
                #pragma unroll
                for (int mt = 0; mt < 4; mt++) {
                    float v0 = cc ? va[mt].y : va[mt].x;   // row m0+g
                    float v1 = cc ? vb[mt].y : vb[mt].x;   // row m0+8+g
                    v0 = v0 > 0.f ? v0 : 0.1f * v0;
                    v1 = v1 > 0.f ? v1 : 0.1f * v1;
                    rmax[mt * 2 + 0] = fmaxf(rmax[mt * 2 + 0], v0 - pen);
                    rmax[mt * 2 + 1] = fmaxf(rmax[mt * 2 + 1], v1 - pen);
                    vmax = fmaxf(vmax, fmaxf(v0, v1));
                }
                colpart[j * 2 + cc] = vmax;
            }
        }
        // column max across the 8 quad-groups (lanes differing in g)
        #pragma unroll
        for (int off = 4; off <= 16; off <<= 1)
            #pragma unroll
            for (int i = 0; i < 16; i++)
                colpart[i] = fmaxf(colpart[i], __shfl_xor_sync(0xffffffffu, colpart[i], off));
        if (g == 0) {
            #pragma unroll
            for (int j = 0; j < 8; j++)
                #pragma unroll
                for (int cc = 0; cc < 2; cc++)
                    fsm[COLWF + wm * NTILE + wn * 64 + j * 8 + 2 * tig + cc] =
                        colpart[j * 2 + cc];
        }
        __syncthreads();
        {
            const int c = tid;   // 0..255
            const float cm = fmaxf(fsm[COLWF + c], fsm[COLWF + NTILE + c]);
            colsum += cm * fsm[MASKF + n0 + c];
        }
        __syncthreads();
    }

    // ---- row-max combine (within quad, then across wn groups) ----
    #pragma unroll
    for (int off = 1; off <= 2; off <<= 1)
        #pragma unroll
        for (int i = 0; i < 8; i++)
            rmax[i] = fmaxf(rmax[i], __shfl_xor_sync(0xffffffffu, rmax[i], off));
    if (tig == 0) {
        #pragma unroll
        for (int mt = 0; mt < 4; mt++) {
            fsm[ROWREDF + (wm * 64 + mt * 16 +     g) * 4 + wn] = rmax[mt * 2 + 0];
            fsm[ROWREDF + (wm * 64 + mt * 16 + 8 + g) * 4 + wn] = rmax[mt * 2 + 1];
        }
    }
    __syncthreads();

    float rpart = 0.f;
    if (tid < 128) {
        rpart = fmaxf(fmaxf(fsm[ROWREDF + tid * 4 + 0], fsm[ROWREDF + tid * 4 + 1]),
                      fmaxf(fsm[ROWREDF + tid * 4 + 2], fsm[ROWREDF + tid * 4 + 3]));
    }

    // ---- block reduction of rpart / colsum / masksum ----
    #pragma unroll
    for (int off = 16; off > 0; off >>= 1) {
        rpart   += __shfl_down_sync(0xffffffffu, rpart,   off);
        colsum  += __shfl_down_sync(0xffffffffu, colsum,  off);
        masksum += __shfl_down_sync(0xffffffffu, masksum, off);
    }
    if (lane == 0) {
        fsm[REDF + w * 4 + 0] = rpart;
        fsm[REDF + w * 4 + 1] = colsum;
        fsm[REDF + w * 4 + 2] = masksum;
    }
    __syncthreads();
    if (tid == 0) {
        float rs = 0.f, cs = 0.f, ms = 0.f;
        #pragma unroll
        for (int i = 0; i < 8; i++) {
            rs += fsm[REDF + i * 4 + 0];
            cs += fsm[REDF + i * 4 + 1];
            ms += fsm[REDF + i * 4 + 2];
        }
        out[b] = rs * (1.f / 128.f) + cs / (ms + 1e-8f);
    }
}

// ---------------------------------------------------------------------------
// Host launch
// ---------------------------------------------------------------------------
extern "C" void kernel_launch(void* const* d_in, const int* in_sizes, int n_in,
                              void* d_out, int out_size)
{
    (void)in_sizes; (void)n_in; (void)out_size;
    const float* patch = (const float*)d_in[0];  // (B, N, C)
    const float* word  = (const float*)d_in[1];  // (B, M, C)
    const float* mask  = (const float*)d_in[2];  // (B, N)
    float* out = (float*)d_out;                  // (B, 1)

    cudaFuncSetAttribute(hrpa_kernel,
                         cudaFuncAttributeMaxDynamicSharedMemorySize, SMEM_BYTES);
    hrpa_kernel<<<B_, 256, SMEM_BYTES>>>(patch, word, mask, out);
}